// round 1
// baseline (speedup 1.0000x reference)
#include <cuda_runtime.h>
#include <math.h>
#include <stdint.h>

#define NPTS 16384
#define CD   256
#define TOPK 20
#define CHUNK 2048
#define NCHUNK (NPTS/CHUNK)

// -------- scratch (static __device__, no allocations) --------
__device__ float g_xn  [NPTS*CD];                 // 16 MB
__device__ float g_sim [(size_t)CHUNK*NPTS];      // 128 MB
__device__ int   g_idx [NPTS*TOPK];               // 1.3 MB
__device__ float g_Am  [NPTS*CD];
__device__ float g_Bm  [NPTS*CD];
__device__ float g_R   [NPTS*CD];
__device__ float g_hagg[NPTS*CD];
__device__ float g_H   [NPTS*CD];

static __device__ __forceinline__ float4 ld4(const float* p){
    return *reinterpret_cast<const float4*>(p);
}

// ================= row normalize =================
__global__ __launch_bounds__(256) void rownorm_kernel(const float* __restrict__ x){
    int i = blockIdx.x;
    int t = threadIdx.x;
    float v = x[i*CD + t];
    float s = v*v;
    #pragma unroll
    for (int off=16; off; off>>=1) s += __shfl_xor_sync(0xffffffffu, s, off);
    __shared__ float red[8];
    if ((t & 31) == 0) red[t>>5] = s;
    __syncthreads();
    float tot = red[0]+red[1]+red[2]+red[3]+red[4]+red[5]+red[6]+red[7];
    float rn = 1.0f / fmaxf(sqrtf(tot), 1e-8f);
    g_xn[i*CD + t] = v * rn;
}

// ================= sim = xn @ xn^T (NT), one 2048-row chunk =================
// BM=BN=128, BK=16, 256 threads, 8x8 register tile, double-buffered smem.
__global__ __launch_bounds__(256,2) void sim_nt_kernel(int rowBase)
{
    __shared__ float As[2][16][132];
    __shared__ float Bs[2][16][132];
    const int tid = threadIdx.x;
    const float* __restrict__ A = g_xn + (size_t)(rowBase + blockIdx.y*128)*CD;
    const float* __restrict__ B = g_xn + (size_t)(blockIdx.x*128)*CD;
    const int r0 = tid >> 2;            // 0..63
    const int kq = (tid & 3) << 2;      // 0,4,8,12
    const int tx = tid & 15, ty = tid >> 4;
    const int m0 = tx*8, n0 = ty*8;

    float acc[8][8];
    #pragma unroll
    for (int i=0;i<8;i++)
        #pragma unroll
        for (int j=0;j<8;j++) acc[i][j]=0.f;

    float4 va0 = ld4(A + r0*CD + kq);
    float4 va1 = ld4(A + (r0+64)*CD + kq);
    float4 vb0 = ld4(B + r0*CD + kq);
    float4 vb1 = ld4(B + (r0+64)*CD + kq);

    As[0][kq+0][r0]=va0.x; As[0][kq+1][r0]=va0.y; As[0][kq+2][r0]=va0.z; As[0][kq+3][r0]=va0.w;
    As[0][kq+0][r0+64]=va1.x; As[0][kq+1][r0+64]=va1.y; As[0][kq+2][r0+64]=va1.z; As[0][kq+3][r0+64]=va1.w;
    Bs[0][kq+0][r0]=vb0.x; Bs[0][kq+1][r0]=vb0.y; Bs[0][kq+2][r0]=vb0.z; Bs[0][kq+3][r0]=vb0.w;
    Bs[0][kq+0][r0+64]=vb1.x; Bs[0][kq+1][r0+64]=vb1.y; Bs[0][kq+2][r0+64]=vb1.z; Bs[0][kq+3][r0+64]=vb1.w;
    __syncthreads();

    int buf = 0;
    for (int s=0; s<16; s++){
        if (s < 15){
            int kk = (s+1)*16;
            va0 = ld4(A + r0*CD + kk + kq);
            va1 = ld4(A + (r0+64)*CD + kk + kq);
            vb0 = ld4(B + r0*CD + kk + kq);
            vb1 = ld4(B + (r0+64)*CD + kk + kq);
        }
        #pragma unroll
        for (int k=0;k<16;k++){
            float4 a0 = *(const float4*)&As[buf][k][m0];
            float4 a1 = *(const float4*)&As[buf][k][m0+4];
            float4 b0 = *(const float4*)&Bs[buf][k][n0];
            float4 b1 = *(const float4*)&Bs[buf][k][n0+4];
            float av[8] = {a0.x,a0.y,a0.z,a0.w,a1.x,a1.y,a1.z,a1.w};
            float bw[8] = {b0.x,b0.y,b0.z,b0.w,b1.x,b1.y,b1.z,b1.w};
            #pragma unroll
            for (int i=0;i<8;i++)
                #pragma unroll
                for (int j=0;j<8;j++)
                    acc[i][j] = fmaf(av[i], bw[j], acc[i][j]);
        }
        if (s < 15){
            int nb = buf ^ 1;
            As[nb][kq+0][r0]=va0.x; As[nb][kq+1][r0]=va0.y; As[nb][kq+2][r0]=va0.z; As[nb][kq+3][r0]=va0.w;
            As[nb][kq+0][r0+64]=va1.x; As[nb][kq+1][r0+64]=va1.y; As[nb][kq+2][r0+64]=va1.z; As[nb][kq+3][r0+64]=va1.w;
            Bs[nb][kq+0][r0]=vb0.x; Bs[nb][kq+1][r0]=vb0.y; Bs[nb][kq+2][r0]=vb0.z; Bs[nb][kq+3][r0]=vb0.w;
            Bs[nb][kq+0][r0+64]=vb1.x; Bs[nb][kq+1][r0+64]=vb1.y; Bs[nb][kq+2][r0+64]=vb1.z; Bs[nb][kq+3][r0+64]=vb1.w;
            __syncthreads();
            buf = nb;
        }
    }

    float* C = g_sim + (size_t)(blockIdx.y*128)*NPTS + blockIdx.x*128;
    #pragma unroll
    for (int i=0;i<8;i++){
        *(float4*)&C[(size_t)(m0+i)*NPTS + n0  ] = make_float4(acc[i][0],acc[i][1],acc[i][2],acc[i][3]);
        *(float4*)&C[(size_t)(m0+i)*NPTS + n0+4] = make_float4(acc[i][4],acc[i][5],acc[i][6],acc[i][7]);
    }
}

// ================= top-20 per row (tie-break: lowest index) =================
__global__ __launch_bounds__(256) void topk_kernel(int rowBase)
{
    const int row = blockIdx.x;            // chunk-local
    const float* __restrict__ S = g_sim + (size_t)row * NPTS;
    const int tid = threadIdx.x;

    float v[TOPK]; int id[TOPK];
    #pragma unroll
    for (int t=0;t<TOPK;t++){ v[t] = -1e30f; id[t] = 1<<30; }
    float thr = -1e30f;

    for (int c = tid; c < NPTS; c += 256){
        float s = S[c];
        if (s > thr){
            int p = TOPK-1;
            while (p > 0 && v[p-1] < s){ v[p]=v[p-1]; id[p]=id[p-1]; --p; }
            v[p]=s; id[p]=c;
            thr = v[TOPK-1];
        }
    }

    __shared__ float sv [256*21];
    __shared__ int   sid[256*21];
    __shared__ float wv[8]; __shared__ int wid_[8]; __shared__ int wsl[8];
    #pragma unroll
    for (int t=0;t<TOPK;t++){ sv[tid*21+t]=v[t]; sid[tid*21+t]=id[t]; }
    __syncthreads();

    const int lane = tid & 31, warp = tid >> 5;
    for (int sel=0; sel<TOPK; sel++){
        float bv=-1e30f; int bi=1<<30; int bs=-1;
        #pragma unroll
        for (int t=0;t<TOPK;t++){
            float vv = sv[tid*21+t]; int ii = sid[tid*21+t];
            if (vv > bv || (vv == bv && ii < bi)){ bv=vv; bi=ii; bs=tid*21+t; }
        }
        #pragma unroll
        for (int off=16; off; off>>=1){
            float ov = __shfl_xor_sync(0xffffffffu, bv, off);
            int   oi = __shfl_xor_sync(0xffffffffu, bi, off);
            int   os = __shfl_xor_sync(0xffffffffu, bs, off);
            if (ov > bv || (ov == bv && oi < bi)){ bv=ov; bi=oi; bs=os; }
        }
        if (lane==0){ wv[warp]=bv; wid_[warp]=bi; wsl[warp]=bs; }
        __syncthreads();
        if (tid==0){
            float Bv=wv[0]; int Bi=wid_[0]; int Bsl=wsl[0];
            #pragma unroll
            for (int w=1;w<8;w++){
                if (wv[w] > Bv || (wv[w]==Bv && wid_[w]<Bi)){ Bv=wv[w]; Bi=wid_[w]; Bsl=wsl[w]; }
            }
            g_idx[(size_t)(rowBase+row)*TOPK + sel] = Bi;
            sv[Bsl] = -1e30f;
        }
        __syncthreads();
    }
}

// ================= gather + relu + sum over 20 neighbors =================
__global__ __launch_bounds__(256) void gather_relu_sum_kernel(){
    const int i = blockIdx.x, c = threadIdx.x;
    __shared__ int nb[TOPK];
    if (c < TOPK) nb[c] = g_idx[(size_t)i*TOPK + c];
    __syncthreads();
    float a = g_Am[(size_t)i*CD + c];
    float acc = 0.f;
    #pragma unroll
    for (int k=0;k<TOPK;k++)
        acc += fmaxf(a + g_Bm[(size_t)nb[k]*CD + c], 0.f);
    g_R[(size_t)i*CD + c] = acc;
}

// ================= generic MLP GEMM: C = act(A1@W[0:256] (+A2@W[256:512]) + s*bias) (+res)
// A1/A2: [M,256] row-major; W: [K,256] row-major; M=16384, Ncols=256.
__global__ __launch_bounds__(256,2) void mlp_gemm_kernel(
    const float* __restrict__ A1, const float* __restrict__ A2,
    const float* __restrict__ W, int nslab,
    const float* __restrict__ bias, float biasScale,
    int doRelu, const float* __restrict__ res,
    float* __restrict__ Cout)
{
    __shared__ float As[2][16][132];
    __shared__ float Bs[2][16][132];
    const int tid = threadIdx.x;
    const int r0 = tid >> 2, kq = (tid & 3) << 2;
    const int kr0 = tid >> 5, nq = (tid & 31) << 2;
    const int tx = tid & 15, ty = tid >> 4;
    const int m0 = tx*8, n0 = ty*8;

    const size_t rowOff = (size_t)blockIdx.y*128*CD;
    const float* A1b = A1 + rowOff;
    const float* A2b = A2 ? (A2 + rowOff) : A1b;
    const float* Wb  = W + blockIdx.x*128;

    float acc[8][8];
    #pragma unroll
    for (int i=0;i<8;i++)
        #pragma unroll
        for (int j=0;j<8;j++) acc[i][j]=0.f;

    // prologue (slab 0 always from A1)
    float4 va0 = ld4(A1b + r0*CD + kq);
    float4 va1 = ld4(A1b + (r0+64)*CD + kq);
    float4 vb0 = ld4(Wb + (size_t)kr0*CD + nq);
    float4 vb1 = ld4(Wb + (size_t)(kr0+8)*CD + nq);

    As[0][kq+0][r0]=va0.x; As[0][kq+1][r0]=va0.y; As[0][kq+2][r0]=va0.z; As[0][kq+3][r0]=va0.w;
    As[0][kq+0][r0+64]=va1.x; As[0][kq+1][r0+64]=va1.y; As[0][kq+2][r0+64]=va1.z; As[0][kq+3][r0+64]=va1.w;
    *(float4*)&Bs[0][kr0  ][nq] = vb0;
    *(float4*)&Bs[0][kr0+8][nq] = vb1;
    __syncthreads();

    int buf = 0;
    for (int s=0; s<nslab; s++){
        if (s+1 < nslab){
            int kk = (s+1)*16;
            const float* Ag = (kk < 256) ? (A1b + kk) : (A2b + (kk-256));
            va0 = ld4(Ag + r0*CD + kq);
            va1 = ld4(Ag + (r0+64)*CD + kq);
            vb0 = ld4(Wb + (size_t)(kk+kr0)*CD + nq);
            vb1 = ld4(Wb + (size_t)(kk+kr0+8)*CD + nq);
        }
        #pragma unroll
        for (int k=0;k<16;k++){
            float4 a0 = *(const float4*)&As[buf][k][m0];
            float4 a1 = *(const float4*)&As[buf][k][m0+4];
            float4 b0 = *(const float4*)&Bs[buf][k][n0];
            float4 b1 = *(const float4*)&Bs[buf][k][n0+4];
            float av[8] = {a0.x,a0.y,a0.z,a0.w,a1.x,a1.y,a1.z,a1.w};
            float bw[8] = {b0.x,b0.y,b0.z,b0.w,b1.x,b1.y,b1.z,b1.w};
            #pragma unroll
            for (int i=0;i<8;i++)
                #pragma unroll
                for (int j=0;j<8;j++)
                    acc[i][j] = fmaf(av[i], bw[j], acc[i][j]);
        }
        if (s+1 < nslab){
            int nb = buf ^ 1;
            As[nb][kq+0][r0]=va0.x; As[nb][kq+1][r0]=va0.y; As[nb][kq+2][r0]=va0.z; As[nb][kq+3][r0]=va0.w;
            As[nb][kq+0][r0+64]=va1.x; As[nb][kq+1][r0+64]=va1.y; As[nb][kq+2][r0+64]=va1.z; As[nb][kq+3][r0+64]=va1.w;
            *(float4*)&Bs[nb][kr0  ][nq] = vb0;
            *(float4*)&Bs[nb][kr0+8][nq] = vb1;
            __syncthreads();
            buf = nb;
        }
    }

    float bv_[8];
    if (bias){
        float4 t0 = ld4(bias + blockIdx.x*128 + n0);
        float4 t1 = ld4(bias + blockIdx.x*128 + n0 + 4);
        bv_[0]=t0.x*biasScale; bv_[1]=t0.y*biasScale; bv_[2]=t0.z*biasScale; bv_[3]=t0.w*biasScale;
        bv_[4]=t1.x*biasScale; bv_[5]=t1.y*biasScale; bv_[6]=t1.z*biasScale; bv_[7]=t1.w*biasScale;
    } else {
        #pragma unroll
        for (int j=0;j<8;j++) bv_[j]=0.f;
    }

    float* Cb = Cout + (size_t)blockIdx.y*128*CD + blockIdx.x*128;
    const float* Rb = res ? (res + (size_t)blockIdx.y*128*CD + blockIdx.x*128) : nullptr;
    #pragma unroll
    for (int i=0;i<8;i++){
        float o[8];
        #pragma unroll
        for (int j=0;j<8;j++){
            float t = acc[i][j] + bv_[j];
            if (doRelu) t = fmaxf(t, 0.f);
            o[j] = t;
        }
        if (Rb){
            float4 q0 = ld4(Rb + (size_t)(m0+i)*CD + n0);
            float4 q1 = ld4(Rb + (size_t)(m0+i)*CD + n0 + 4);
            o[0]+=q0.x; o[1]+=q0.y; o[2]+=q0.z; o[3]+=q0.w;
            o[4]+=q1.x; o[5]+=q1.y; o[6]+=q1.z; o[7]+=q1.w;
        }
        *(float4*)&Cb[(size_t)(m0+i)*CD + n0  ] = make_float4(o[0],o[1],o[2],o[3]);
        *(float4*)&Cb[(size_t)(m0+i)*CD + n0+4] = make_float4(o[4],o[5],o[6],o[7]);
    }
}

// ================= launch =================
extern "C" void kernel_launch(void* const* d_in, const int* in_sizes, int n_in,
                              void* d_out, int out_size)
{
    const float* x   = (const float*)d_in[0];
    const float* W1m = (const float*)d_in[1];
    const float* b1m = (const float*)d_in[2];
    const float* W2m = (const float*)d_in[3];
    const float* b2m = (const float*)d_in[4];
    const float* W1u = (const float*)d_in[5];
    const float* b1u = (const float*)d_in[6];
    const float* W2u = (const float*)d_in[7];
    const float* b2u = (const float*)d_in[8];
    float* out = (float*)d_out;

    float *p_Am=nullptr, *p_Bm=nullptr, *p_R=nullptr, *p_hagg=nullptr, *p_H=nullptr;
    cudaGetSymbolAddress((void**)&p_Am,   g_Am);
    cudaGetSymbolAddress((void**)&p_Bm,   g_Bm);
    cudaGetSymbolAddress((void**)&p_R,    g_R);
    cudaGetSymbolAddress((void**)&p_hagg, g_hagg);
    cudaGetSymbolAddress((void**)&p_H,    g_H);

    rownorm_kernel<<<NPTS, 256>>>(x);

    // A_msg = x @ W1_msg[0:256] + b1_msg ; B_msg = x @ W1_msg[256:512]
    mlp_gemm_kernel<<<dim3(2,128), 256>>>(x, nullptr, W1m,          16, b1m, 1.f, 0, nullptr, p_Am);
    mlp_gemm_kernel<<<dim3(2,128), 256>>>(x, nullptr, W1m + 256*CD, 16, nullptr, 0.f, 0, nullptr, p_Bm);

    // sim + topk in row chunks
    for (int cb = 0; cb < NCHUNK; cb++){
        sim_nt_kernel<<<dim3(128,16), 256>>>(cb*CHUNK);
        topk_kernel  <<<CHUNK, 256>>>(cb*CHUNK);
    }

    // R_i = sum_j relu(A_i + B_j)
    gather_relu_sum_kernel<<<NPTS, 256>>>();

    // h_agg = R @ W2_msg + 20*b2_msg
    mlp_gemm_kernel<<<dim3(2,128), 256>>>(p_R, nullptr, W2m, 16, b2m, (float)TOPK, 0, nullptr, p_hagg);

    // H = relu(x @ W1u[0:256] + h_agg @ W1u[256:512] + b1u)
    mlp_gemm_kernel<<<dim3(2,128), 256>>>(x, p_hagg, W1u, 32, b1u, 1.f, 1, nullptr, p_H);

    // out = x + H @ W2_upd + b2_upd
    mlp_gemm_kernel<<<dim3(2,128), 256>>>(p_H, nullptr, W2u, 16, b2u, 1.f, 0, x, out);
}

// round 2
// speedup vs baseline: 3.8025x; 3.8025x over previous
#include <cuda_runtime.h>
#include <math.h>
#include <stdint.h>

#define NPTS 16384
#define CD   256
#define TOPK 20
#define CHUNK 2048
#define NCHUNK (NPTS/CHUNK)
#define TK_BUF 2048

// -------- scratch (static __device__, no allocations) --------
__device__ float g_xn  [NPTS*CD];                 // 16 MB
__device__ float g_sim [(size_t)CHUNK*NPTS];      // 128 MB
__device__ int   g_idx [NPTS*TOPK];               // 1.3 MB
__device__ float g_Am  [NPTS*CD];
__device__ float g_Bm  [NPTS*CD];
__device__ float g_R   [NPTS*CD];
__device__ float g_hagg[NPTS*CD];
__device__ float g_H   [NPTS*CD];

static __device__ __forceinline__ float4 ld4(const float* p){
    return *reinterpret_cast<const float4*>(p);
}

// ================= row normalize =================
__global__ __launch_bounds__(256) void rownorm_kernel(const float* __restrict__ x){
    int i = blockIdx.x;
    int t = threadIdx.x;
    float v = x[i*CD + t];
    float s = v*v;
    #pragma unroll
    for (int off=16; off; off>>=1) s += __shfl_xor_sync(0xffffffffu, s, off);
    __shared__ float red[8];
    if ((t & 31) == 0) red[t>>5] = s;
    __syncthreads();
    float tot = red[0]+red[1]+red[2]+red[3]+red[4]+red[5]+red[6]+red[7];
    float rn = 1.0f / fmaxf(sqrtf(tot), 1e-8f);
    g_xn[i*CD + t] = v * rn;
}

// ================= sim = xn @ xn^T (NT), one 2048-row chunk =================
__global__ __launch_bounds__(256,2) void sim_nt_kernel(int rowBase)
{
    __shared__ float As[2][16][132];
    __shared__ float Bs[2][16][132];
    const int tid = threadIdx.x;
    const float* __restrict__ A = g_xn + (size_t)(rowBase + blockIdx.y*128)*CD;
    const float* __restrict__ B = g_xn + (size_t)(blockIdx.x*128)*CD;
    const int r0 = tid >> 2;            // 0..63
    const int kq = (tid & 3) << 2;      // 0,4,8,12
    const int tx = tid & 15, ty = tid >> 4;
    const int m0 = tx*8, n0 = ty*8;

    float acc[8][8];
    #pragma unroll
    for (int i=0;i<8;i++)
        #pragma unroll
        for (int j=0;j<8;j++) acc[i][j]=0.f;

    float4 va0 = ld4(A + r0*CD + kq);
    float4 va1 = ld4(A + (r0+64)*CD + kq);
    float4 vb0 = ld4(B + r0*CD + kq);
    float4 vb1 = ld4(B + (r0+64)*CD + kq);

    As[0][kq+0][r0]=va0.x; As[0][kq+1][r0]=va0.y; As[0][kq+2][r0]=va0.z; As[0][kq+3][r0]=va0.w;
    As[0][kq+0][r0+64]=va1.x; As[0][kq+1][r0+64]=va1.y; As[0][kq+2][r0+64]=va1.z; As[0][kq+3][r0+64]=va1.w;
    Bs[0][kq+0][r0]=vb0.x; Bs[0][kq+1][r0]=vb0.y; Bs[0][kq+2][r0]=vb0.z; Bs[0][kq+3][r0]=vb0.w;
    Bs[0][kq+0][r0+64]=vb1.x; Bs[0][kq+1][r0+64]=vb1.y; Bs[0][kq+2][r0+64]=vb1.z; Bs[0][kq+3][r0+64]=vb1.w;
    __syncthreads();

    int buf = 0;
    for (int s=0; s<16; s++){
        if (s < 15){
            int kk = (s+1)*16;
            va0 = ld4(A + r0*CD + kk + kq);
            va1 = ld4(A + (r0+64)*CD + kk + kq);
            vb0 = ld4(B + r0*CD + kk + kq);
            vb1 = ld4(B + (r0+64)*CD + kk + kq);
        }
        #pragma unroll
        for (int k=0;k<16;k++){
            float4 a0 = *(const float4*)&As[buf][k][m0];
            float4 a1 = *(const float4*)&As[buf][k][m0+4];
            float4 b0 = *(const float4*)&Bs[buf][k][n0];
            float4 b1 = *(const float4*)&Bs[buf][k][n0+4];
            float av[8] = {a0.x,a0.y,a0.z,a0.w,a1.x,a1.y,a1.z,a1.w};
            float bw[8] = {b0.x,b0.y,b0.z,b0.w,b1.x,b1.y,b1.z,b1.w};
            #pragma unroll
            for (int i=0;i<8;i++)
                #pragma unroll
                for (int j=0;j<8;j++)
                    acc[i][j] = fmaf(av[i], bw[j], acc[i][j]);
        }
        if (s < 15){
            int nb = buf ^ 1;
            As[nb][kq+0][r0]=va0.x; As[nb][kq+1][r0]=va0.y; As[nb][kq+2][r0]=va0.z; As[nb][kq+3][r0]=va0.w;
            As[nb][kq+0][r0+64]=va1.x; As[nb][kq+1][r0+64]=va1.y; As[nb][kq+2][r0+64]=va1.z; As[nb][kq+3][r0+64]=va1.w;
            Bs[nb][kq+0][r0]=vb0.x; Bs[nb][kq+1][r0]=vb0.y; Bs[nb][kq+2][r0]=vb0.z; Bs[nb][kq+3][r0]=vb0.w;
            Bs[nb][kq+0][r0+64]=vb1.x; Bs[nb][kq+1][r0+64]=vb1.y; Bs[nb][kq+2][r0+64]=vb1.z; Bs[nb][kq+3][r0+64]=vb1.w;
            __syncthreads();
            buf = nb;
        }
    }

    float* C = g_sim + (size_t)(blockIdx.y*128)*NPTS + blockIdx.x*128;
    #pragma unroll
    for (int i=0;i<8;i++){
        *(float4*)&C[(size_t)(m0+i)*NPTS + n0  ] = make_float4(acc[i][0],acc[i][1],acc[i][2],acc[i][3]);
        *(float4*)&C[(size_t)(m0+i)*NPTS + n0+4] = make_float4(acc[i][4],acc[i][5],acc[i][6],acc[i][7]);
    }
}

// ================= top-20 per row: threshold filter + exact select =================
// tau = 20th largest of 256 per-thread maxima is a provably valid lower bound
// on the row's 20th largest value (>=20 elements >= tau, and v20 >= tau).
__global__ __launch_bounds__(256) void topk_kernel(int rowBase)
{
    const int row = blockIdx.x;            // chunk-local
    const float* __restrict__ S = g_sim + (size_t)row * NPTS;
    const float4* __restrict__ S4 = (const float4*)S;
    const int tid = threadIdx.x;
    const int lane = tid & 31, warp = tid >> 5;

    __shared__ float s_max[256];
    __shared__ float s_tau;
    __shared__ int   s_cnt;
    __shared__ float cv[TK_BUF];
    __shared__ int   ci[TK_BUF];

    // Phase A: per-thread max over 64 strided values
    float m = -1e30f;
    #pragma unroll
    for (int j=0;j<16;j++){
        float4 v = S4[tid + 256*j];
        m = fmaxf(m, fmaxf(fmaxf(v.x,v.y), fmaxf(v.z,v.w)));
    }
    s_max[tid] = m;
    if (tid == 0) s_cnt = 0;
    __syncthreads();

    // Phase T: warp 0 finds 20th largest of the 256 maxima
    if (warp == 0){
        float a[8];
        #pragma unroll
        for (int j=0;j<8;j++) a[j] = s_max[lane*8 + j];
        // sort a[0..7] descending (19-comparator network)
        #define CSW(i,j) { if (a[i] < a[j]) { float t=a[i]; a[i]=a[j]; a[j]=t; } }
        CSW(0,1) CSW(2,3) CSW(4,5) CSW(6,7)
        CSW(0,2) CSW(1,3) CSW(4,6) CSW(5,7)
        CSW(1,2) CSW(5,6) CSW(0,4) CSW(3,7)
        CSW(1,5) CSW(2,6)
        CSW(1,4) CSW(3,6)
        CSW(2,4) CSW(3,5)
        CSW(3,4)
        #undef CSW
        float tau = -1e30f;
        for (int sel = 0; sel < TOPK; sel++){
            float h = a[0];
            float bv = h;
            #pragma unroll
            for (int off=16; off; off>>=1)
                bv = fmaxf(bv, __shfl_xor_sync(0xffffffffu, bv, off));
            unsigned ball = __ballot_sync(0xffffffffu, h == bv);
            if (lane == (__ffs(ball) - 1)){
                #pragma unroll
                for (int j=0;j<7;j++) a[j] = a[j+1];
                a[7] = -1e30f;
            }
            tau = bv;
        }
        if (lane == 0) s_tau = tau;
    }
    __syncthreads();
    const float tau = s_tau;

    // Phase B: collect candidates >= tau (expected ~21)
    #pragma unroll
    for (int j=0;j<16;j++){
        float4 v = S4[tid + 256*j];
        int base = (tid + 256*j) * 4;
        if (v.x >= tau){ int p = atomicAdd(&s_cnt,1); if (p < TK_BUF){ cv[p]=v.x; ci[p]=base+0; } }
        if (v.y >= tau){ int p = atomicAdd(&s_cnt,1); if (p < TK_BUF){ cv[p]=v.y; ci[p]=base+1; } }
        if (v.z >= tau){ int p = atomicAdd(&s_cnt,1); if (p < TK_BUF){ cv[p]=v.z; ci[p]=base+2; } }
        if (v.w >= tau){ int p = atomicAdd(&s_cnt,1); if (p < TK_BUF){ cv[p]=v.w; ci[p]=base+3; } }
    }
    __syncthreads();
    int cnt = s_cnt < TK_BUF ? s_cnt : TK_BUF;

    // Phase C: warp 0 selects top-20 (tie-break: lowest index)
    if (warp == 0){
        for (int sel = 0; sel < TOPK; sel++){
            float bv = -1e30f; int bi = 0x7fffffff; int bp = -1;
            for (int p = lane; p < cnt; p += 32){
                float vv = cv[p]; int ii = ci[p];
                if (vv > bv || (vv == bv && ii < bi)){ bv = vv; bi = ii; bp = p; }
            }
            #pragma unroll
            for (int off=16; off; off>>=1){
                float ov = __shfl_xor_sync(0xffffffffu, bv, off);
                int   oi = __shfl_xor_sync(0xffffffffu, bi, off);
                int   op = __shfl_xor_sync(0xffffffffu, bp, off);
                if (ov > bv || (ov == bv && oi < bi)){ bv = ov; bi = oi; bp = op; }
            }
            if (lane == 0){
                g_idx[(size_t)(rowBase + row)*TOPK + sel] = bi;
                cv[bp] = -1e30f;
            }
            __syncwarp();
        }
    }
}

// ================= gather + relu + sum over 20 neighbors =================
__global__ __launch_bounds__(256) void gather_relu_sum_kernel(){
    const int i = blockIdx.x, c = threadIdx.x;
    __shared__ int nb[TOPK];
    if (c < TOPK) nb[c] = g_idx[(size_t)i*TOPK + c];
    __syncthreads();
    float a = g_Am[(size_t)i*CD + c];
    float acc = 0.f;
    #pragma unroll
    for (int k=0;k<TOPK;k++)
        acc += fmaxf(a + g_Bm[(size_t)nb[k]*CD + c], 0.f);
    g_R[(size_t)i*CD + c] = acc;
}

// ================= generic MLP GEMM =================
__global__ __launch_bounds__(256,2) void mlp_gemm_kernel(
    const float* __restrict__ A1, const float* __restrict__ A2,
    const float* __restrict__ W, int nslab,
    const float* __restrict__ bias, float biasScale,
    int doRelu, const float* __restrict__ res,
    float* __restrict__ Cout)
{
    __shared__ float As[2][16][132];
    __shared__ float Bs[2][16][132];
    const int tid = threadIdx.x;
    const int r0 = tid >> 2, kq = (tid & 3) << 2;
    const int kr0 = tid >> 5, nq = (tid & 31) << 2;
    const int tx = tid & 15, ty = tid >> 4;
    const int m0 = tx*8, n0 = ty*8;

    const size_t rowOff = (size_t)blockIdx.y*128*CD;
    const float* A1b = A1 + rowOff;
    const float* A2b = A2 ? (A2 + rowOff) : A1b;
    const float* Wb  = W + blockIdx.x*128;

    float acc[8][8];
    #pragma unroll
    for (int i=0;i<8;i++)
        #pragma unroll
        for (int j=0;j<8;j++) acc[i][j]=0.f;

    float4 va0 = ld4(A1b + r0*CD + kq);
    float4 va1 = ld4(A1b + (r0+64)*CD + kq);
    float4 vb0 = ld4(Wb + (size_t)kr0*CD + nq);
    float4 vb1 = ld4(Wb + (size_t)(kr0+8)*CD + nq);

    As[0][kq+0][r0]=va0.x; As[0][kq+1][r0]=va0.y; As[0][kq+2][r0]=va0.z; As[0][kq+3][r0]=va0.w;
    As[0][kq+0][r0+64]=va1.x; As[0][kq+1][r0+64]=va1.y; As[0][kq+2][r0+64]=va1.z; As[0][kq+3][r0+64]=va1.w;
    *(float4*)&Bs[0][kr0  ][nq] = vb0;
    *(float4*)&Bs[0][kr0+8][nq] = vb1;
    __syncthreads();

    int buf = 0;
    for (int s=0; s<nslab; s++){
        if (s+1 < nslab){
            int kk = (s+1)*16;
            const float* Ag = (kk < 256) ? (A1b + kk) : (A2b + (kk-256));
            va0 = ld4(Ag + r0*CD + kq);
            va1 = ld4(Ag + (r0+64)*CD + kq);
            vb0 = ld4(Wb + (size_t)(kk+kr0)*CD + nq);
            vb1 = ld4(Wb + (size_t)(kk+kr0+8)*CD + nq);
        }
        #pragma unroll
        for (int k=0;k<16;k++){
            float4 a0 = *(const float4*)&As[buf][k][m0];
            float4 a1 = *(const float4*)&As[buf][k][m0+4];
            float4 b0 = *(const float4*)&Bs[buf][k][n0];
            float4 b1 = *(const float4*)&Bs[buf][k][n0+4];
            float av[8] = {a0.x,a0.y,a0.z,a0.w,a1.x,a1.y,a1.z,a1.w};
            float bw[8] = {b0.x,b0.y,b0.z,b0.w,b1.x,b1.y,b1.z,b1.w};
            #pragma unroll
            for (int i=0;i<8;i++)
                #pragma unroll
                for (int j=0;j<8;j++)
                    acc[i][j] = fmaf(av[i], bw[j], acc[i][j]);
        }
        if (s+1 < nslab){
            int nb = buf ^ 1;
            As[nb][kq+0][r0]=va0.x; As[nb][kq+1][r0]=va0.y; As[nb][kq+2][r0]=va0.z; As[nb][kq+3][r0]=va0.w;
            As[nb][kq+0][r0+64]=va1.x; As[nb][kq+1][r0+64]=va1.y; As[nb][kq+2][r0+64]=va1.z; As[nb][kq+3][r0+64]=va1.w;
            *(float4*)&Bs[nb][kr0  ][nq] = vb0;
            *(float4*)&Bs[nb][kr0+8][nq] = vb1;
            __syncthreads();
            buf = nb;
        }
    }

    float bv_[8];
    if (bias){
        float4 t0 = ld4(bias + blockIdx.x*128 + n0);
        float4 t1 = ld4(bias + blockIdx.x*128 + n0 + 4);
        bv_[0]=t0.x*biasScale; bv_[1]=t0.y*biasScale; bv_[2]=t0.z*biasScale; bv_[3]=t0.w*biasScale;
        bv_[4]=t1.x*biasScale; bv_[5]=t1.y*biasScale; bv_[6]=t1.z*biasScale; bv_[7]=t1.w*biasScale;
    } else {
        #pragma unroll
        for (int j=0;j<8;j++) bv_[j]=0.f;
    }

    float* Cb = Cout + (size_t)blockIdx.y*128*CD + blockIdx.x*128;
    const float* Rb = res ? (res + (size_t)blockIdx.y*128*CD + blockIdx.x*128) : nullptr;
    #pragma unroll
    for (int i=0;i<8;i++){
        float o[8];
        #pragma unroll
        for (int j=0;j<8;j++){
            float t = acc[i][j] + bv_[j];
            if (doRelu) t = fmaxf(t, 0.f);
            o[j] = t;
        }
        if (Rb){
            float4 q0 = ld4(Rb + (size_t)(m0+i)*CD + n0);
            float4 q1 = ld4(Rb + (size_t)(m0+i)*CD + n0 + 4);
            o[0]+=q0.x; o[1]+=q0.y; o[2]+=q0.z; o[3]+=q0.w;
            o[4]+=q1.x; o[5]+=q1.y; o[6]+=q1.z; o[7]+=q1.w;
        }
        *(float4*)&Cb[(size_t)(m0+i)*CD + n0  ] = make_float4(o[0],o[1],o[2],o[3]);
        *(float4*)&Cb[(size_t)(m0+i)*CD + n0+4] = make_float4(o[4],o[5],o[6],o[7]);
    }
}

// ================= launch =================
extern "C" void kernel_launch(void* const* d_in, const int* in_sizes, int n_in,
                              void* d_out, int out_size)
{
    const float* x   = (const float*)d_in[0];
    const float* W1m = (const float*)d_in[1];
    const float* b1m = (const float*)d_in[2];
    const float* W2m = (const float*)d_in[3];
    const float* b2m = (const float*)d_in[4];
    const float* W1u = (const float*)d_in[5];
    const float* b1u = (const float*)d_in[6];
    const float* W2u = (const float*)d_in[7];
    const float* b2u = (const float*)d_in[8];
    float* out = (float*)d_out;

    float *p_Am=nullptr, *p_Bm=nullptr, *p_R=nullptr, *p_hagg=nullptr, *p_H=nullptr;
    cudaGetSymbolAddress((void**)&p_Am,   g_Am);
    cudaGetSymbolAddress((void**)&p_Bm,   g_Bm);
    cudaGetSymbolAddress((void**)&p_R,    g_R);
    cudaGetSymbolAddress((void**)&p_hagg, g_hagg);
    cudaGetSymbolAddress((void**)&p_H,    g_H);

    rownorm_kernel<<<NPTS, 256>>>(x);

    // A_msg = x @ W1_msg[0:256] + b1_msg ; B_msg = x @ W1_msg[256:512]
    mlp_gemm_kernel<<<dim3(2,128), 256>>>(x, nullptr, W1m,          16, b1m, 1.f, 0, nullptr, p_Am);
    mlp_gemm_kernel<<<dim3(2,128), 256>>>(x, nullptr, W1m + 256*CD, 16, nullptr, 0.f, 0, nullptr, p_Bm);

    // sim + topk in row chunks
    for (int cb = 0; cb < NCHUNK; cb++){
        sim_nt_kernel<<<dim3(128,16), 256>>>(cb*CHUNK);
        topk_kernel  <<<CHUNK, 256>>>(cb*CHUNK);
    }

    // R_i = sum_j relu(A_i + B_j)
    gather_relu_sum_kernel<<<NPTS, 256>>>();

    // h_agg = R @ W2_msg + 20*b2_msg
    mlp_gemm_kernel<<<dim3(2,128), 256>>>(p_R, nullptr, W2m, 16, b2m, (float)TOPK, 0, nullptr, p_hagg);

    // H = relu(x @ W1u[0:256] + h_agg @ W1u[256:512] + b1u)
    mlp_gemm_kernel<<<dim3(2,128), 256>>>(x, p_hagg, W1u, 32, b1u, 1.f, 1, nullptr, p_H);

    // out = x + H @ W2_upd + b2_upd
    mlp_gemm_kernel<<<dim3(2,128), 256>>>(p_H, nullptr, W2u, 16, b2u, 1.f, 0, x, out);
}

// round 5
// speedup vs baseline: 4.2340x; 1.1135x over previous
#include <cuda_runtime.h>
#include <math.h>
#include <stdint.h>

#define NPTS 16384
#define CD   256
#define KHL  512          // hi|lo concatenated K
#define TOPK 20
#define CAND 40           // candidate pool guaranteed to contain true top-CAND
#define CHUNK 2048
#define NCHUNK (NPTS/CHUNK)
#define TK_BUF 2048

#define SROW 36           // padded smem row stride (floats)
#define TILE (128*SROW)

// -------- scratch (static __device__, no allocations) --------
__device__ float g_xn  [(size_t)NPTS*CD];         // fp32 normalized rows (for exact rescore)
__device__ float g_hl  [(size_t)NPTS*KHL];        // [:,0:256]=hi tf32, [:,256:512]=lo tf32
__device__ float g_sim [(size_t)CHUNK*NPTS];      // 128 MB
__device__ int   g_idx [NPTS*TOPK];
__device__ float g_Am  [NPTS*CD];
__device__ float g_Bm  [NPTS*CD];
__device__ float g_R   [NPTS*CD];
__device__ float g_hagg[NPTS*CD];
__device__ float g_H   [NPTS*CD];

static __device__ __forceinline__ float4 ld4(const float* p){
    return *reinterpret_cast<const float4*>(p);
}

// ================= row normalize + tf32 split (hi | lo) =================
__global__ __launch_bounds__(256) void rownorm_split_kernel(const float* __restrict__ x){
    int i = blockIdx.x;
    int t = threadIdx.x;
    float v = x[i*CD + t];
    float s = v*v;
    #pragma unroll
    for (int off=16; off; off>>=1) s += __shfl_xor_sync(0xffffffffu, s, off);
    __shared__ float red[8];
    if ((t & 31) == 0) red[t>>5] = s;
    __syncthreads();
    float tot = red[0]+red[1]+red[2]+red[3]+red[4]+red[5]+red[6]+red[7];
    float rn = 1.0f / fmaxf(sqrtf(tot), 1e-8f);
    float xn = v * rn;
    g_xn[(size_t)i*CD + t] = xn;
    uint32_t hb, lb;
    asm("cvt.rna.tf32.f32 %0, %1;" : "=r"(hb) : "f"(xn));
    float hi = __uint_as_float(hb);
    float lo = xn - hi;
    asm("cvt.rna.tf32.f32 %0, %1;" : "=r"(lb) : "f"(lo));
    g_hl[(size_t)i*KHL + t]       = hi;
    g_hl[(size_t)i*KHL + 256 + t] = __uint_as_float(lb);
}

// ================= sim via mma.sync tf32, K=512 =================
// Block tile 128x128, 8 warps in 4(m) x 2(n), warp tile 32x64 (m16n8k8 frags).
__global__ __launch_bounds__(256,2) void sim_mma_kernel(int rowBase)
{
    extern __shared__ float smem[];
    float* As = smem;              // [2][128][SROW]
    float* Bs = smem + 2*TILE;     // [2][128][SROW]

    const int tid  = threadIdx.x;
    const int warp = tid >> 5, lane = tid & 31;
    const int wr   = warp >> 1;          // 0..3 (m)
    const int wc   = warp & 1;           // 0..1 (n)
    const int g    = lane >> 2;          // 0..7
    const int tg   = lane & 3;           // 0..3

    const size_t rowA0 = (size_t)rowBase + (size_t)blockIdx.y * 128;
    const size_t rowB0 = (size_t)blockIdx.x * 128;
    const float* __restrict__ gA = g_hl + rowA0 * KHL;
    const float* __restrict__ gB = g_hl + rowB0 * KHL;

    float acc[2][8][4];
    #pragma unroll
    for (int mi=0;mi<2;mi++)
        #pragma unroll
        for (int nj=0;nj<8;nj++)
            #pragma unroll
            for (int q=0;q<4;q++) acc[mi][nj][q]=0.f;

    const int fr[4] = { (tid + 0)   >> 3, (tid + 256) >> 3, (tid + 512) >> 3, (tid + 768) >> 3 };
    const int fc = (tid & 7) * 4;

    // prologue: fill buf 0 for kc=0
    #pragma unroll
    for (int p=0;p<4;p++){
        *(float4*)&As[fr[p]*SROW + fc] = ld4(gA + (size_t)fr[p]*KHL + fc);
        *(float4*)&Bs[fr[p]*SROW + fc] = ld4(gB + (size_t)fr[p]*KHL + fc);
    }
    __syncthreads();

    int buf = 0;
    #pragma unroll 1
    for (int kc = 0; kc < 16; kc++){
        float4 va[4], vb[4];
        if (kc < 15){
            const int ko = (kc+1)*32 + fc;
            #pragma unroll
            for (int p=0;p<4;p++){
                va[p] = ld4(gA + (size_t)fr[p]*KHL + ko);
                vb[p] = ld4(gB + (size_t)fr[p]*KHL + ko);
            }
        }

        const float* Ab = &As[buf*TILE + (wr*32)*SROW];
        const float* Bb = &Bs[buf*TILE + (wc*64)*SROW];
        #pragma unroll
        for (int k8=0;k8<4;k8++){
            const int kb = k8*8;
            uint32_t a[2][4];
            #pragma unroll
            for (int mi=0;mi<2;mi++){
                const float* ap = Ab + (mi*16)*SROW + kb;
                a[mi][0] = __float_as_uint(ap[(g  )*SROW + tg  ]);
                a[mi][1] = __float_as_uint(ap[(g+8)*SROW + tg  ]);
                a[mi][2] = __float_as_uint(ap[(g  )*SROW + tg+4]);
                a[mi][3] = __float_as_uint(ap[(g+8)*SROW + tg+4]);
            }
            #pragma unroll
            for (int nj=0;nj<8;nj++){
                const float* bp = Bb + (nj*8)*SROW + kb;
                uint32_t b0 = __float_as_uint(bp[g*SROW + tg  ]);
                uint32_t b1 = __float_as_uint(bp[g*SROW + tg+4]);
                #pragma unroll
                for (int mi=0;mi<2;mi++){
                    asm volatile(
                        "mma.sync.aligned.m16n8k8.row.col.f32.tf32.tf32.f32 "
                        "{%0,%1,%2,%3}, {%4,%5,%6,%7}, {%8,%9}, {%0,%1,%2,%3};"
                        : "+f"(acc[mi][nj][0]), "+f"(acc[mi][nj][1]),
                          "+f"(acc[mi][nj][2]), "+f"(acc[mi][nj][3])
                        : "r"(a[mi][0]), "r"(a[mi][1]), "r"(a[mi][2]), "r"(a[mi][3]),
                          "r"(b0), "r"(b1));
                }
            }
        }

        if (kc < 15){
            const int nb = buf ^ 1;
            #pragma unroll
            for (int p=0;p<4;p++){
                *(float4*)&As[nb*TILE + fr[p]*SROW + fc] = va[p];
                *(float4*)&Bs[nb*TILE + fr[p]*SROW + fc] = vb[p];
            }
            __syncthreads();
            buf = nb;
        }
    }

    // epilogue
    float* C = g_sim + ((size_t)blockIdx.y*128 + wr*32 + g) * NPTS
                     + rowB0 + wc*64 + 2*tg;
    #pragma unroll
    for (int mi=0;mi<2;mi++){
        #pragma unroll
        for (int nj=0;nj<8;nj++){
            float* c0 = C + (size_t)(mi*16)*NPTS + nj*8;
            *(float2*)c0                     = make_float2(acc[mi][nj][0], acc[mi][nj][1]);
            *(float2*)(c0 + (size_t)8*NPTS)  = make_float2(acc[mi][nj][2], acc[mi][nj][3]);
        }
    }
}

// ================= top-20: approx candidates (>= tau40) + exact fp32 rescore =================
__global__ __launch_bounds__(256) void topk_kernel(int rowBase)
{
    const int row  = blockIdx.x;           // chunk-local
    const int rowG = rowBase + row;
    const float* __restrict__ S = g_sim + (size_t)row * NPTS;
    const float4* __restrict__ S4 = (const float4*)S;
    const int tid = threadIdx.x;
    const int lane = tid & 31, warp = tid >> 5;

    __shared__ float s_max[256];
    __shared__ float s_tau;
    __shared__ int   s_cnt;
    __shared__ float cv[TK_BUF];
    __shared__ int   ci[TK_BUF];
    __shared__ float xi[CD];

    // Phase A: per-thread max over 64 strided values; also stage row i
    xi[tid] = g_xn[(size_t)rowG*CD + tid];
    float m = -1e30f;
    #pragma unroll
    for (int j=0;j<16;j++){
        float4 v = S4[tid + 256*j];
        m = fmaxf(m, fmaxf(fmaxf(v.x,v.y), fmaxf(v.z,v.w)));
    }
    s_max[tid] = m;
    if (tid == 0) s_cnt = 0;
    __syncthreads();

    // Phase T: warp 0 finds CAND-th largest of the 256 maxima (valid filter for top-CAND)
    if (warp == 0){
        float a[8];
        #pragma unroll
        for (int j=0;j<8;j++) a[j] = s_max[lane*8 + j];
        #define CSW(i,j) { if (a[i] < a[j]) { float t=a[i]; a[i]=a[j]; a[j]=t; } }
        CSW(0,1) CSW(2,3) CSW(4,5) CSW(6,7)
        CSW(0,2) CSW(1,3) CSW(4,6) CSW(5,7)
        CSW(1,2) CSW(5,6) CSW(0,4) CSW(3,7)
        CSW(1,5) CSW(2,6)
        CSW(1,4) CSW(3,6)
        CSW(2,4) CSW(3,5)
        CSW(3,4)
        #undef CSW
        float tau = -1e30f;
        for (int sel = 0; sel < CAND; sel++){
            float h = a[0];
            float bv = h;
            #pragma unroll
            for (int off=16; off; off>>=1)
                bv = fmaxf(bv, __shfl_xor_sync(0xffffffffu, bv, off));
            unsigned ball = __ballot_sync(0xffffffffu, h == bv);
            if (lane == (__ffs(ball) - 1)){
                #pragma unroll
                for (int j=0;j<7;j++) a[j] = a[j+1];
                a[7] = -1e30f;
            }
            tau = bv;
        }
        if (lane == 0) s_tau = tau;
    }
    __syncthreads();
    const float tau = s_tau;

    // Phase B: collect candidates >= tau (expected ~CAND+1)
    #pragma unroll
    for (int j=0;j<16;j++){
        float4 v = S4[tid + 256*j];
        int base = (tid + 256*j) * 4;
        if (v.x >= tau){ int p = atomicAdd(&s_cnt,1); if (p < TK_BUF){ ci[p]=base+0; } }
        if (v.y >= tau){ int p = atomicAdd(&s_cnt,1); if (p < TK_BUF){ ci[p]=base+1; } }
        if (v.z >= tau){ int p = atomicAdd(&s_cnt,1); if (p < TK_BUF){ ci[p]=base+2; } }
        if (v.w >= tau){ int p = atomicAdd(&s_cnt,1); if (p < TK_BUF){ ci[p]=base+3; } }
    }
    __syncthreads();
    int cnt = s_cnt < TK_BUF ? s_cnt : TK_BUF;

    // Phase C: exact fp32 rescore — serial k-ascending fmaf chain (bit-identical
    // to the fp32 GEMM accumulation that matched the reference's selections)
    for (int p = tid; p < cnt; p += 256){
        const float* __restrict__ xj = g_xn + (size_t)ci[p]*CD;
        float acc = 0.f;
        #pragma unroll 8
        for (int k = 0; k < CD; k++)
            acc = fmaf(xi[k], xj[k], acc);
        cv[p] = acc;
    }
    __syncthreads();

    // Phase D: warp 0 selects top-20 by exact values (tie-break: lowest index)
    if (warp == 0){
        for (int sel = 0; sel < TOPK; sel++){
            float bv = -1e30f; int bi = 0x7fffffff; int bp = -1;
            for (int p = lane; p < cnt; p += 32){
                float vv = cv[p]; int ii = ci[p];
                if (vv > bv || (vv == bv && ii < bi)){ bv = vv; bi = ii; bp = p; }
            }
            #pragma unroll
            for (int off=16; off; off>>=1){
                float ov = __shfl_xor_sync(0xffffffffu, bv, off);
                int   oi = __shfl_xor_sync(0xffffffffu, bi, off);
                int   op = __shfl_xor_sync(0xffffffffu, bp, off);
                if (ov > bv || (ov == bv && oi < bi)){ bv = ov; bi = oi; bp = op; }
            }
            if (lane == 0){
                g_idx[(size_t)rowG*TOPK + sel] = bi;
                cv[bp] = -1e30f;
            }
            __syncwarp();
        }
    }
}

// ================= gather + relu + sum over 20 neighbors =================
__global__ __launch_bounds__(256) void gather_relu_sum_kernel(){
    const int i = blockIdx.x, c = threadIdx.x;
    __shared__ int nb[TOPK];
    if (c < TOPK) nb[c] = g_idx[(size_t)i*TOPK + c];
    __syncthreads();
    float a = g_Am[(size_t)i*CD + c];
    float acc = 0.f;
    #pragma unroll
    for (int k=0;k<TOPK;k++)
        acc += fmaxf(a + g_Bm[(size_t)nb[k]*CD + c], 0.f);
    g_R[(size_t)i*CD + c] = acc;
}

// ================= generic MLP GEMM =================
__global__ __launch_bounds__(256,2) void mlp_gemm_kernel(
    const float* __restrict__ A1, const float* __restrict__ A2,
    const float* __restrict__ W, int nslab,
    const float* __restrict__ bias, float biasScale,
    int doRelu, const float* __restrict__ res,
    float* __restrict__ Cout)
{
    __shared__ float As[2][16][132];
    __shared__ float Bs[2][16][132];
    const int tid = threadIdx.x;
    const int r0 = tid >> 2, kq = (tid & 3) << 2;
    const int kr0 = tid >> 5, nq = (tid & 31) << 2;
    const int tx = tid & 15, ty = tid >> 4;
    const int m0 = tx*8, n0 = ty*8;

    const size_t rowOff = (size_t)blockIdx.y*128*CD;
    const float* A1b = A1 + rowOff;
    const float* A2b = A2 ? (A2 + rowOff) : A1b;
    const float* Wb  = W + blockIdx.x*128;

    float acc[8][8];
    #pragma unroll
    for (int i=0;i<8;i++)
        #pragma unroll
        for (int j=0;j<8;j++) acc[i][j]=0.f;

    float4 va0 = ld4(A1b + r0*CD + kq);
    float4 va1 = ld4(A1b + (r0+64)*CD + kq);
    float4 vb0 = ld4(Wb + (size_t)kr0*CD + nq);
    float4 vb1 = ld4(Wb + (size_t)(kr0+8)*CD + nq);

    As[0][kq+0][r0]=va0.x; As[0][kq+1][r0]=va0.y; As[0][kq+2][r0]=va0.z; As[0][kq+3][r0]=va0.w;
    As[0][kq+0][r0+64]=va1.x; As[0][kq+1][r0+64]=va1.y; As[0][kq+2][r0+64]=va1.z; As[0][kq+3][r0+64]=va1.w;
    *(float4*)&Bs[0][kr0  ][nq] = vb0;
    *(float4*)&Bs[0][kr0+8][nq] = vb1;
    __syncthreads();

    int buf = 0;
    for (int s=0; s<nslab; s++){
        if (s+1 < nslab){
            int kk = (s+1)*16;
            const float* Ag = (kk < 256) ? (A1b + kk) : (A2b + (kk-256));
            va0 = ld4(Ag + r0*CD + kq);
            va1 = ld4(Ag + (r0+64)*CD + kq);
            vb0 = ld4(Wb + (size_t)(kk+kr0)*CD + nq);
            vb1 = ld4(Wb + (size_t)(kk+kr0+8)*CD + nq);
        }
        #pragma unroll
        for (int k=0;k<16;k++){
            float4 a0 = *(const float4*)&As[buf][k][m0];
            float4 a1 = *(const float4*)&As[buf][k][m0+4];
            float4 b0 = *(const float4*)&Bs[buf][k][n0];
            float4 b1 = *(const float4*)&Bs[buf][k][n0+4];
            float av[8] = {a0.x,a0.y,a0.z,a0.w,a1.x,a1.y,a1.z,a1.w};
            float bw[8] = {b0.x,b0.y,b0.z,b0.w,b1.x,b1.y,b1.z,b1.w};
            #pragma unroll
            for (int i=0;i<8;i++)
                #pragma unroll
                for (int j=0;j<8;j++)
                    acc[i][j] = fmaf(av[i], bw[j], acc[i][j]);
        }
        if (s+1 < nslab){
            int nb = buf ^ 1;
            As[nb][kq+0][r0]=va0.x; As[nb][kq+1][r0]=va0.y; As[nb][kq+2][r0]=va0.z; As[nb][kq+3][r0]=va0.w;
            As[nb][kq+0][r0+64]=va1.x; As[nb][kq+1][r0+64]=va1.y; As[nb][kq+2][r0+64]=va1.z; As[nb][kq+3][r0+64]=va1.w;
            *(float4*)&Bs[nb][kr0  ][nq] = vb0;
            *(float4*)&Bs[nb][kr0+8][nq] = vb1;
            __syncthreads();
            buf = nb;
        }
    }

    float bv_[8];
    if (bias){
        float4 t0 = ld4(bias + blockIdx.x*128 + n0);
        float4 t1 = ld4(bias + blockIdx.x*128 + n0 + 4);
        bv_[0]=t0.x*biasScale; bv_[1]=t0.y*biasScale; bv_[2]=t0.z*biasScale; bv_[3]=t0.w*biasScale;
        bv_[4]=t1.x*biasScale; bv_[5]=t1.y*biasScale; bv_[6]=t1.z*biasScale; bv_[7]=t1.w*biasScale;
    } else {
        #pragma unroll
        for (int j=0;j<8;j++) bv_[j]=0.f;
    }

    float* Cb = Cout + (size_t)blockIdx.y*128*CD + blockIdx.x*128;
    const float* Rb = res ? (res + (size_t)blockIdx.y*128*CD + blockIdx.x*128) : nullptr;
    #pragma unroll
    for (int i=0;i<8;i++){
        float o[8];
        #pragma unroll
        for (int j=0;j<8;j++){
            float t = acc[i][j] + bv_[j];
            if (doRelu) t = fmaxf(t, 0.f);
            o[j] = t;
        }
        if (Rb){
            float4 q0 = ld4(Rb + (size_t)(m0+i)*CD + n0);
            float4 q1 = ld4(Rb + (size_t)(m0+i)*CD + n0 + 4);
            o[0]+=q0.x; o[1]+=q0.y; o[2]+=q0.z; o[3]+=q0.w;
            o[4]+=q1.x; o[5]+=q1.y; o[6]+=q1.z; o[7]+=q1.w;
        }
        *(float4*)&Cb[(size_t)(m0+i)*CD + n0  ] = make_float4(o[0],o[1],o[2],o[3]);
        *(float4*)&Cb[(size_t)(m0+i)*CD + n0+4] = make_float4(o[4],o[5],o[6],o[7]);
    }
}

// ================= launch =================
extern "C" void kernel_launch(void* const* d_in, const int* in_sizes, int n_in,
                              void* d_out, int out_size)
{
    const float* x   = (const float*)d_in[0];
    const float* W1m = (const float*)d_in[1];
    const float* b1m = (const float*)d_in[2];
    const float* W2m = (const float*)d_in[3];
    const float* b2m = (const float*)d_in[4];
    const float* W1u = (const float*)d_in[5];
    const float* b1u = (const float*)d_in[6];
    const float* W2u = (const float*)d_in[7];
    const float* b2u = (const float*)d_in[8];
    float* out = (float*)d_out;

    float *p_Am=nullptr, *p_Bm=nullptr, *p_R=nullptr, *p_hagg=nullptr, *p_H=nullptr;
    cudaGetSymbolAddress((void**)&p_Am,   g_Am);
    cudaGetSymbolAddress((void**)&p_Bm,   g_Bm);
    cudaGetSymbolAddress((void**)&p_R,    g_R);
    cudaGetSymbolAddress((void**)&p_hagg, g_hagg);
    cudaGetSymbolAddress((void**)&p_H,    g_H);

    const int SIM_SMEM = 4 * TILE * (int)sizeof(float);   // 73728 B
    cudaFuncSetAttribute(sim_mma_kernel, cudaFuncAttributeMaxDynamicSharedMemorySize, SIM_SMEM);

    rownorm_split_kernel<<<NPTS, 256>>>(x);

    // A_msg = x @ W1_msg[0:256] + b1_msg ; B_msg = x @ W1_msg[256:512]
    mlp_gemm_kernel<<<dim3(2,128), 256>>>(x, nullptr, W1m,          16, b1m, 1.f, 0, nullptr, p_Am);
    mlp_gemm_kernel<<<dim3(2,128), 256>>>(x, nullptr, W1m + 256*CD, 16, nullptr, 0.f, 0, nullptr, p_Bm);

    // sim + topk in row chunks
    for (int cb = 0; cb < NCHUNK; cb++){
        sim_mma_kernel<<<dim3(NPTS/128, CHUNK/128), 256, SIM_SMEM>>>(cb*CHUNK);
        topk_kernel  <<<CHUNK, 256>>>(cb*CHUNK);
    }

    // R_i = sum_j relu(A_i + B_j)
    gather_relu_sum_kernel<<<NPTS, 256>>>();

    // h_agg = R @ W2_msg + 20*b2_msg
    mlp_gemm_kernel<<<dim3(2,128), 256>>>(p_R, nullptr, W2m, 16, b2m, (float)TOPK, 0, nullptr, p_hagg);

    // H = relu(x @ W1u[0:256] + h_agg @ W1u[256:512] + b1u)
    mlp_gemm_kernel<<<dim3(2,128), 256>>>(x, p_hagg, W1u, 32, b1u, 1.f, 1, nullptr, p_H);

    // out = x + H @ W2_upd + b2_upd
    mlp_gemm_kernel<<<dim3(2,128), 256>>>(p_H, nullptr, W2u, 16, b2u, 1.f, 0, x, out);
}